// round 1
// baseline (speedup 1.0000x reference)
#include <cuda_runtime.h>

// Problem constants (fixed by the dataset)
#define T_STEPS 500
#define B_SZ    128
#define K_SZ    256   // window W
#define F_SZ    512   // filters
#define C_SZ    10

// Tiling
#define BT 16   // b per CTA
#define FT 32   // f per CTA (= lanes per warp)
#define KW 32   // k per warp
#define NW 8    // warps per CTA
#define NTHREADS 256
#define NCTAS (( B_SZ / BT ) * ( F_SZ / FT ))   // 8 * 16 = 128

// Scratch: spike counts [B, F]
__device__ float g_counts[B_SZ * F_SZ];

__global__ __launch_bounds__(NTHREADS, 1)
void snn_fused_kernel(const float* __restrict__ x,     // [T, B, K]
                      const float* __restrict__ wts)   // [F, K]
{
    __shared__ float xs[BT][K_SZ];          // 16 KB
    __shared__ float psum[NW][BT][FT];      // 16 KB

    const int tid = threadIdx.x;
    const int w   = tid >> 5;        // warp id 0..7  -> K chunk
    const int l   = tid & 31;        // lane -> f within tile
    const int bg  = blockIdx.x & 7;  // b-group 0..7
    const int fg  = blockIdx.x >> 3; // f-group 0..15
    const int b0  = bg * BT;
    const int f   = fg * FT + l;
    const int kb  = w * KW;

    // Per-lane weights live in registers for the whole kernel.
    float wreg[KW];
    {
        const float4* wrow = reinterpret_cast<const float4*>(wts + (size_t)f * K_SZ + kb);
        #pragma unroll
        for (int j = 0; j < KW / 4; ++j) {
            float4 v = wrow[j];
            wreg[4*j+0] = v.x; wreg[4*j+1] = v.y;
            wreg[4*j+2] = v.z; wreg[4*j+3] = v.w;
        }
    }

    // Scan state: this thread owns (b = brow, brow+8) x (f_lane = l)
    const int brow = tid >> 5;  // 0..7 (reuse warp id as b row for the scan phase)
    float u0 = 0.f, u1 = 0.f, tr0 = 0.f, tr1 = 0.f, c0 = 0.f, c1 = 0.f;

    const float4* __restrict__ xg = reinterpret_cast<const float4*>(x);
    float4* xs4 = reinterpret_cast<float4*>(&xs[0][0]);

    for (int t = 0; t < T_STEPS; ++t) {
        // Stage x[t, b0:b0+16, :] -> smem (1024 float4, 4 per thread, coalesced)
        const float4* src = xg + (size_t)t * (B_SZ * K_SZ / 4) + (size_t)b0 * (K_SZ / 4);
        #pragma unroll
        for (int i = 0; i < (BT * K_SZ / 4) / NTHREADS; ++i)
            xs4[tid + NTHREADS * i] = src[tid + NTHREADS * i];
        __syncthreads();

        // Each warp: partial dot over its K chunk for all 16 b rows.
        // x loads are LDS.128 broadcasts (all lanes same address); weights in regs.
        #pragma unroll 4
        for (int b = 0; b < BT; ++b) {
            const float4* xrow = reinterpret_cast<const float4*>(&xs[b][kb]);
            float a0 = 0.f, a1 = 0.f, a2 = 0.f, a3 = 0.f;
            #pragma unroll
            for (int j = 0; j < KW / 4; ++j) {
                float4 xv = xrow[j];
                a0 = fmaf(xv.x, wreg[4*j+0], a0);
                a1 = fmaf(xv.y, wreg[4*j+1], a1);
                a2 = fmaf(xv.z, wreg[4*j+2], a2);
                a3 = fmaf(xv.w, wreg[4*j+3], a3);
            }
            psum[w][b][l] = (a0 + a1) + (a2 + a3);
        }
        __syncthreads();

        // Reduce 8 K-chunk partials and advance the LIF scan (registers only).
        float p0 = 0.f, p1 = 0.f;
        #pragma unroll
        for (int ww = 0; ww < NW; ++ww) {
            p0 += psum[ww][brow][l];
            p1 += psum[ww][brow + 8][l];
        }
        tr0 = 0.95f * tr0 + p0;
        u0  = 0.90f * u0 + tr0;
        if (u0 > 1.0f) { c0 += 1.0f; u0 = 0.0f; }

        tr1 = 0.95f * tr1 + p1;
        u1  = 0.90f * u1 + tr1;
        if (u1 > 1.0f) { c1 += 1.0f; u1 = 0.0f; }
        // Next iteration's xs writes are ordered by the loop-top __syncthreads;
        // psum re-writes are ordered because every thread passed its own psum
        // reads before arriving at that barrier.
    }

    g_counts[(size_t)(b0 + brow)     * F_SZ + f] = c0;
    g_counts[(size_t)(b0 + brow + 8) * F_SZ + f] = c1;
}

// Decoder: out[b, c] = sum_f counts[b,f] * dec_w[c,f] + dec_b[c]
// 128 blocks (one per b), 320 threads = 10 classes x 32 lanes.
__global__ __launch_bounds__(320, 1)
void snn_decode_kernel(const float* __restrict__ dec_w,  // [C, F]
                       const float* __restrict__ dec_b,  // [C]
                       float* __restrict__ out)          // [B, C]
{
    const int b = blockIdx.x;
    const int c = threadIdx.x >> 5;
    const int l = threadIdx.x & 31;

    const float* cnt = g_counts + (size_t)b * F_SZ;
    const float* dwr = dec_w + (size_t)c * F_SZ;
    float s = 0.f;
    #pragma unroll
    for (int f = l; f < F_SZ; f += 32)
        s += cnt[f] * dwr[f];
    #pragma unroll
    for (int o = 16; o > 0; o >>= 1)
        s += __shfl_down_sync(0xffffffffu, s, o);
    if (l == 0)
        out[b * C_SZ + c] = s + dec_b[c];
}

extern "C" void kernel_launch(void* const* d_in, const int* in_sizes, int n_in,
                              void* d_out, int out_size)
{
    const float* x     = (const float*)d_in[0];  // [500,128,256]
    const float* wts   = (const float*)d_in[1];  // [512,256]
    const float* dec_w = (const float*)d_in[2];  // [10,512]
    const float* dec_b = (const float*)d_in[3];  // [10]
    float* out = (float*)d_out;                  // [128,10]

    snn_fused_kernel<<<NCTAS, NTHREADS>>>(x, wts);
    snn_decode_kernel<<<B_SZ, 320>>>(dec_w, dec_b, out);
}

// round 3
// speedup vs baseline: 1.4270x; 1.4270x over previous
#include <cuda_runtime.h>

// Problem constants
#define T_STEPS 500
#define B_SZ    128
#define K_SZ    256
#define F_SZ    512
#define C_SZ    10

// Tiling: CTA = 16 b x 32 f, 16 warps, each warp owns a K-chunk of 16.
#define BT 16
#define FT 32
#define KW 16
#define NW 16
#define NTHREADS 512
#define NCTAS ((B_SZ / BT) * (F_SZ / FT))   // 8 * 16 = 128

// Dynamic smem layout: xs[2][BT][K_SZ] followed by psum[2][NW][BT][FT]
#define XS_FLOATS   (2 * BT * K_SZ)                 // 8192 floats = 32 KB
#define PSUM_FLOATS (2 * NW * BT * FT)              // 16384 floats = 64 KB
#define SMEM_BYTES  ((XS_FLOATS + PSUM_FLOATS) * 4) // 96 KB

__device__ float g_counts[B_SZ * F_SZ];

// ---- packed f32x2 helpers (Blackwell) ----
__device__ __forceinline__ unsigned long long pack2(float lo, float hi) {
    unsigned long long d;
    asm("mov.b64 %0, {%1, %2};" : "=l"(d) : "r"(__float_as_uint(lo)), "r"(__float_as_uint(hi)));
    return d;
}
__device__ __forceinline__ void fma2(unsigned long long& d, unsigned long long a, unsigned long long b) {
    asm("fma.rn.f32x2 %0, %1, %2, %0;" : "+l"(d) : "l"(a), "l"(b));
}
__device__ __forceinline__ unsigned long long add2(unsigned long long a, unsigned long long b) {
    unsigned long long d;
    asm("add.rn.f32x2 %0, %1, %2;" : "=l"(d) : "l"(a), "l"(b));
    return d;
}
__device__ __forceinline__ float lo_plus_hi(unsigned long long v) {
    unsigned int lo, hi;
    asm("mov.b64 {%0, %1}, %2;" : "=r"(lo), "=r"(hi) : "l"(v));
    return __uint_as_float(lo) + __uint_as_float(hi);
}

__global__ __launch_bounds__(NTHREADS, 1)
void snn_fused_kernel(const float* __restrict__ x,     // [T, B, K]
                      const float* __restrict__ wts)   // [F, K]
{
    extern __shared__ float smem[];
    // xs[buf][b][k], psum[buf][w][b][l]
    float* xs_base   = smem;
    float* psum_base = smem + XS_FLOATS;

    const int tid = threadIdx.x;
    const int w   = tid >> 5;        // warp id 0..15: K-chunk owner AND b-row owner (scan)
    const int l   = tid & 31;        // lane -> f within tile
    const int bg  = blockIdx.x & 7;
    const int fg  = blockIdx.x >> 3;
    const int b0  = bg * BT;
    const int f   = fg * FT + l;
    const int kb  = w * KW;

    // Weights: 16 floats per lane, pre-packed into 8 f32x2 register pairs.
    unsigned long long wp[KW / 2];
    {
        const float4* wrow = reinterpret_cast<const float4*>(wts + (size_t)f * K_SZ + kb);
        #pragma unroll
        for (int j = 0; j < KW / 4; ++j) {
            float4 v = wrow[j];
            wp[2 * j + 0] = pack2(v.x, v.y);
            wp[2 * j + 1] = pack2(v.z, v.w);
        }
    }

    // Staging: tile = 16 b x 256 k = 1024 float4; 512 threads -> 2 float4 each.
    const float4* __restrict__ xg = reinterpret_cast<const float4*>(x);
    float4* xs0 = reinterpret_cast<float4*>(xs_base);
    float4* xs1 = reinterpret_cast<float4*>(xs_base + BT * K_SZ);
    const size_t t_stride = (size_t)B_SZ * K_SZ / 4;
    const size_t b_off    = (size_t)b0 * (K_SZ / 4);

    // Prologue: stage t = 0
    {
        const float4* src = xg + b_off;
        xs0[tid]       = src[tid];
        xs0[tid + 512] = src[tid + 512];
    }
    __syncthreads();

    // Scan state: one (b=w, f) neuron per thread.
    float u = 0.f, tr = 0.f, cnt = 0.f;

    for (int t = 0; t < T_STEPS; ++t) {
        const int cur = t & 1;
        const float* xs_cur = xs_base + cur * (BT * K_SZ);
        float* psum_cur     = psum_base + cur * (NW * BT * FT);
        float4* xs_nxt      = cur ? xs0 : xs1;

        // Kick off global loads for t+1 early (hidden under compute).
        float4 r0, r1;
        const bool more = (t + 1 < T_STEPS);
        if (more) {
            const float4* src = xg + (size_t)(t + 1) * t_stride + b_off;
            r0 = src[tid];
            r1 = src[tid + 512];
        }

        // Partial dot products over this warp's K-chunk, all 16 b rows.
        // x from smem as packed f32x2 (LDS.128 broadcast), weights packed in regs.
        #pragma unroll 4
        for (int b = 0; b < BT; ++b) {
            const ulonglong2* xrow =
                reinterpret_cast<const ulonglong2*>(xs_cur + b * K_SZ + kb);
            unsigned long long acc0 = 0ULL, acc1 = 0ULL;
            #pragma unroll
            for (int j = 0; j < KW / 4; ++j) {
                ulonglong2 xv = xrow[j];
                fma2(acc0, xv.x, wp[2 * j + 0]);
                fma2(acc1, xv.y, wp[2 * j + 1]);
            }
            psum_cur[(w * BT + b) * FT + l] = lo_plus_hi(add2(acc0, acc1));
        }

        // Commit t+1 stage into the other buffer.
        if (more) {
            xs_nxt[tid]       = r0;
            xs_nxt[tid + 512] = r1;
        }
        __syncthreads();

        // Reduce the 16 K-chunk partials for this thread's (b=w, f) and scan.
        float p = 0.f;
        #pragma unroll
        for (int ww = 0; ww < NW; ++ww)
            p += psum_cur[(ww * BT + w) * FT + l];

        tr = 0.95f * tr + p;
        u  = 0.90f * u + tr;
        if (u > 1.0f) { cnt += 1.0f; u = 0.0f; }
        // psum[cur] next rewritten at t+2 (separated by barrier t+1) -> safe.
        // xs[nxt] last read at t-1 (separated by barrier t-1) -> safe.
    }

    g_counts[(size_t)(b0 + w) * F_SZ + f] = cnt;
}

// Decoder: out[b, c] = sum_f counts[b,f] * dec_w[c,f] + dec_b[c]
__global__ __launch_bounds__(320, 1)
void snn_decode_kernel(const float* __restrict__ dec_w,  // [C, F]
                       const float* __restrict__ dec_b,  // [C]
                       float* __restrict__ out)          // [B, C]
{
    const int b = blockIdx.x;
    const int c = threadIdx.x >> 5;
    const int l = threadIdx.x & 31;

    const float* cnt = g_counts + (size_t)b * F_SZ;
    const float* dwr = dec_w + (size_t)c * F_SZ;
    float s = 0.f;
    #pragma unroll
    for (int fi = l; fi < F_SZ; fi += 32)
        s += cnt[fi] * dwr[fi];
    #pragma unroll
    for (int o = 16; o > 0; o >>= 1)
        s += __shfl_down_sync(0xffffffffu, s, o);
    if (l == 0)
        out[b * C_SZ + c] = s + dec_b[c];
}

extern "C" void kernel_launch(void* const* d_in, const int* in_sizes, int n_in,
                              void* d_out, int out_size)
{
    const float* x     = (const float*)d_in[0];  // [500,128,256]
    const float* wts   = (const float*)d_in[1];  // [512,256]
    const float* dec_w = (const float*)d_in[2];  // [10,512]
    const float* dec_b = (const float*)d_in[3];  // [10]
    float* out = (float*)d_out;                  // [128,10]

    // Opt in to >48 KB dynamic shared memory (function attribute; not an alloc,
    // idempotent, and legal outside/inside graph capture).
    cudaFuncSetAttribute(snn_fused_kernel,
                         cudaFuncAttributeMaxDynamicSharedMemorySize, SMEM_BYTES);

    snn_fused_kernel<<<NCTAS, NTHREADS, SMEM_BYTES>>>(x, wts);
    snn_decode_kernel<<<B_SZ, 320>>>(dec_w, dec_b, out);
}

// round 5
// speedup vs baseline: 4.1483x; 2.9071x over previous
#include <cuda_runtime.h>
#include <cuda_bf16.h>
#include <cstdint>

// Problem constants
#define T_STEPS 500
#define B_SZ    128
#define K_SZ    256
#define F_SZ    512
#define C_SZ    10
#define MROWS   (T_STEPS * B_SZ)   // 64000

// GEMM tiling: CTA 128(M) x 128(N), 8 warps of 64x32, K chunk 64, 3 bf16 terms.
#define TM 128
#define TN 128
#define KC 64
#define NCHUNK (K_SZ / KC)   // 4
#define GT 256               // GEMM threads

// Padded smem rows: 64 data bf16 + 8 pad = 72 bf16 = 144 B (conflict-free ldmatrix)
#define PITCHB     144
#define TILEBYTES  (128 * PITCHB)      // 18432 per (array, stage)
#define STAGEBYTES (4 * TILEBYTES)     // Ahi, Alo, Bhi, Blo
#define SMEM_TOTAL (2 * STAGEBYTES)    // double buffered = 147456 B

// Scratch
__device__ float g_proj[MROWS * F_SZ];            // 131 MB
__device__ float g_counts[B_SZ * F_SZ];
__device__ __nv_bfloat16 g_xhi[MROWS * K_SZ];     // 32.8 MB
__device__ __nv_bfloat16 g_xlo[MROWS * K_SZ];
__device__ __nv_bfloat16 g_whi[F_SZ * K_SZ];
__device__ __nv_bfloat16 g_wlo[F_SZ * K_SZ];

// ---------------- helpers ----------------
__device__ __forceinline__ uint32_t smem_u32(const void* p) {
    uint32_t a;
    asm("{ .reg .u64 t; cvta.to.shared.u64 t, %1; cvt.u32.u64 %0, t; }" : "=r"(a) : "l"(p));
    return a;
}
__device__ __forceinline__ void cp_async16(uint32_t dst, const void* src) {
    asm volatile("cp.async.cg.shared.global [%0], [%1], 16;" :: "r"(dst), "l"(src) : "memory");
}
#define CP_COMMIT() asm volatile("cp.async.commit_group;" ::: "memory")

__device__ __forceinline__ void ldmx4(uint32_t* r, uint32_t addr) {
    asm volatile("ldmatrix.sync.aligned.m8n8.x4.shared.b16 {%0,%1,%2,%3}, [%4];"
                 : "=r"(r[0]), "=r"(r[1]), "=r"(r[2]), "=r"(r[3]) : "r"(addr));
}
__device__ __forceinline__ void mma_bf16(float* c, const uint32_t* a, const uint32_t* b) {
    asm volatile(
        "mma.sync.aligned.m16n8k16.row.col.f32.bf16.bf16.f32 "
        "{%0,%1,%2,%3}, {%4,%5,%6,%7}, {%8,%9}, {%0,%1,%2,%3};"
        : "+f"(c[0]), "+f"(c[1]), "+f"(c[2]), "+f"(c[3])
        : "r"(a[0]), "r"(a[1]), "r"(a[2]), "r"(a[3]), "r"(b[0]), "r"(b[1]));
}

// ---------------- Pass 0: fp32 -> bf16 hi/lo split ----------------
__global__ void convert_split_kernel(const float4* __restrict__ src,
                                     uint2* __restrict__ hi, uint2* __restrict__ lo, int n4)
{
    int i = blockIdx.x * blockDim.x + threadIdx.x;
    if (i >= n4) return;
    float4 v = src[i];
    __nv_bfloat16 h0 = __float2bfloat16(v.x), h1 = __float2bfloat16(v.y);
    __nv_bfloat16 h2 = __float2bfloat16(v.z), h3 = __float2bfloat16(v.w);
    __nv_bfloat16 l0 = __float2bfloat16(v.x - __bfloat162float(h0));
    __nv_bfloat16 l1 = __float2bfloat16(v.y - __bfloat162float(h1));
    __nv_bfloat16 l2 = __float2bfloat16(v.z - __bfloat162float(h2));
    __nv_bfloat16 l3 = __float2bfloat16(v.w - __bfloat162float(h3));
    uint2 ph, pl;
    ph.x = (uint32_t)*(uint16_t*)&h0 | ((uint32_t)*(uint16_t*)&h1 << 16);
    ph.y = (uint32_t)*(uint16_t*)&h2 | ((uint32_t)*(uint16_t*)&h3 << 16);
    pl.x = (uint32_t)*(uint16_t*)&l0 | ((uint32_t)*(uint16_t*)&l1 << 16);
    pl.y = (uint32_t)*(uint16_t*)&l2 | ((uint32_t)*(uint16_t*)&l3 << 16);
    hi[i] = ph;
    lo[i] = pl;
}

// ---------------- Pass 1: GEMM proj = x @ W^T via mma.sync bf16 ----------------
__device__ __forceinline__ void stage_chunk(uint32_t sb, int s, int c,
                                            int mtile, int ntile, int tid)
{
    const int r = tid >> 3;        // 0..31
    const int u = tid & 7;         // 0..7 (16B units within a 128B row chunk)
    #pragma unroll
    for (int pass = 0; pass < 4; ++pass) {
        const int row = pass * 32 + r;
        const uint32_t d = sb + s * STAGEBYTES + row * PITCHB + u * 16;
        const size_t aoff = (size_t)(mtile * TM + row) * K_SZ + c * KC + u * 8;
        const size_t boff = (size_t)(ntile * TN + row) * K_SZ + c * KC + u * 8;
        cp_async16(d,                 g_xhi + aoff);
        cp_async16(d + TILEBYTES,     g_xlo + aoff);
        cp_async16(d + 2 * TILEBYTES, g_whi + boff);
        cp_async16(d + 3 * TILEBYTES, g_wlo + boff);
    }
}

__global__ __launch_bounds__(GT, 1)
void snn_gemm_kernel()
{
    extern __shared__ char smem[];
    const uint32_t sb = smem_u32(smem);
    const int tid  = threadIdx.x;
    const int lane = tid & 31;
    const int wid  = tid >> 5;
    const int wm   = wid >> 2;      // 0..1 -> 64-row block
    const int wn   = wid & 3;       // 0..3 -> 32-col block
    const int mtile = blockIdx.x;   // 0..499
    const int ntile = blockIdx.y;   // 0..3

    // ldmatrix lane address offset (same formula for A and B tiles)
    const uint32_t laneoff = (uint32_t)((lane & 15) * PITCHB + (lane >> 4) * 16);

    float acc[4][4][4];
    #pragma unroll
    for (int mi = 0; mi < 4; ++mi)
        #pragma unroll
        for (int ni = 0; ni < 4; ++ni)
            #pragma unroll
            for (int q = 0; q < 4; ++q) acc[mi][ni][q] = 0.f;

    stage_chunk(sb, 0, 0, mtile, ntile, tid);
    CP_COMMIT();

    for (int c = 0; c < NCHUNK; ++c) {
        const int s = c & 1;
        if (c + 1 < NCHUNK) {
            stage_chunk(sb, s ^ 1, c + 1, mtile, ntile, tid);
            CP_COMMIT();
            asm volatile("cp.async.wait_group 1;" ::: "memory");
        } else {
            asm volatile("cp.async.wait_group 0;" ::: "memory");
        }
        __syncthreads();

        const uint32_t Ahi_b = sb + s * STAGEBYTES;
        const uint32_t Bhi_b = Ahi_b + 2 * TILEBYTES;

        #pragma unroll
        for (int kk = 0; kk < 4; ++kk) {
            uint32_t ah[4][4], al[4][4];
            #pragma unroll
            for (int mi = 0; mi < 4; ++mi) {
                uint32_t addr = Ahi_b + (uint32_t)((wm * 64 + mi * 16) * PITCHB + kk * 32) + laneoff;
                ldmx4(ah[mi], addr);
                ldmx4(al[mi], addr + TILEBYTES);
            }
            uint32_t bh[4][2], bl[4][2];
            #pragma unroll
            for (int p = 0; p < 2; ++p) {
                uint32_t addr = Bhi_b + (uint32_t)((wn * 32 + p * 16) * PITCHB + kk * 32) + laneoff;
                uint32_t r[4];
                ldmx4(r, addr);
                bh[2*p][0] = r[0]; bh[2*p][1] = r[2];
                bh[2*p+1][0] = r[1]; bh[2*p+1][1] = r[3];
                ldmx4(r, addr + TILEBYTES);
                bl[2*p][0] = r[0]; bl[2*p][1] = r[2];
                bl[2*p+1][0] = r[1]; bl[2*p+1][1] = r[3];
            }
            #pragma unroll
            for (int mi = 0; mi < 4; ++mi)
                #pragma unroll
                for (int ni = 0; ni < 4; ++ni) {
                    mma_bf16(acc[mi][ni], ah[mi], bh[ni]);   // xh * wh
                    mma_bf16(acc[mi][ni], ah[mi], bl[ni]);   // xh * wl
                    mma_bf16(acc[mi][ni], al[mi], bh[ni]);   // xl * wh
                }
        }
        __syncthreads();
    }

    // Epilogue: fragment -> gmem (32B-sector aligned float2 stores)
    const int g  = lane >> 2;
    const int tg = lane & 3;
    #pragma unroll
    for (int mi = 0; mi < 4; ++mi) {
        const int m0 = mtile * TM + wm * 64 + mi * 16 + g;
        #pragma unroll
        for (int ni = 0; ni < 4; ++ni) {
            const int nc = ntile * TN + wn * 32 + ni * 8 + tg * 2;
            float2 v0 = make_float2(acc[mi][ni][0], acc[mi][ni][1]);
            float2 v1 = make_float2(acc[mi][ni][2], acc[mi][ni][3]);
            *reinterpret_cast<float2*>(&g_proj[(size_t)m0 * F_SZ + nc])       = v0;
            *reinterpret_cast<float2*>(&g_proj[(size_t)(m0 + 8) * F_SZ + nc]) = v1;
        }
    }
}

// ---------------- Pass 2: LIF scan ----------------
__global__ __launch_bounds__(512, 1)
void snn_scan_kernel()
{
    const int n = blockIdx.x * 512 + threadIdx.x;   // n = b*512 + f
    const float* p = g_proj + n;
    float u = 0.f, tr = 0.f, cnt = 0.f;
    #pragma unroll 1
    for (int t = 0; t < T_STEPS; t += 10) {
        float v[10];
        #pragma unroll
        for (int j = 0; j < 10; ++j)
            v[j] = p[(size_t)(t + j) * (B_SZ * F_SZ)];
        #pragma unroll
        for (int j = 0; j < 10; ++j) {
            tr = 0.95f * tr + v[j];
            u  = 0.90f * u + tr;
            if (u > 1.0f) { cnt += 1.0f; u = 0.0f; }
        }
    }
    g_counts[n] = cnt;
}

// ---------------- Pass 3: decoder ----------------
__global__ __launch_bounds__(320, 1)
void snn_decode_kernel(const float* __restrict__ dec_w,
                       const float* __restrict__ dec_b,
                       float* __restrict__ out)
{
    const int b = blockIdx.x;
    const int c = threadIdx.x >> 5;
    const int l = threadIdx.x & 31;
    const float* cnt = g_counts + (size_t)b * F_SZ;
    const float* dwr = dec_w + (size_t)c * F_SZ;
    float s = 0.f;
    #pragma unroll
    for (int fi = l; fi < F_SZ; fi += 32)
        s += cnt[fi] * dwr[fi];
    #pragma unroll
    for (int o = 16; o > 0; o >>= 1)
        s += __shfl_down_sync(0xffffffffu, s, o);
    if (l == 0)
        out[b * C_SZ + c] = s + dec_b[c];
}

extern "C" void kernel_launch(void* const* d_in, const int* in_sizes, int n_in,
                              void* d_out, int out_size)
{
    const float* x     = (const float*)d_in[0];  // [500,128,256]
    const float* wts   = (const float*)d_in[1];  // [512,256]
    const float* dec_w = (const float*)d_in[2];  // [10,512]
    const float* dec_b = (const float*)d_in[3];  // [10]
    float* out = (float*)d_out;                  // [128,10]

    // Resolve device-symbol addresses (host-side; graph-capture safe, no allocs).
    static uint2* p_xhi = nullptr; static uint2* p_xlo = nullptr;
    static uint2* p_whi = nullptr; static uint2* p_wlo = nullptr;
    if (!p_xhi) {
        cudaGetSymbolAddress((void**)&p_xhi, g_xhi);
        cudaGetSymbolAddress((void**)&p_xlo, g_xlo);
        cudaGetSymbolAddress((void**)&p_whi, g_whi);
        cudaGetSymbolAddress((void**)&p_wlo, g_wlo);
        cudaFuncSetAttribute(snn_gemm_kernel,
                             cudaFuncAttributeMaxDynamicSharedMemorySize, SMEM_TOTAL);
    }

    const int nx4 = MROWS * K_SZ / 4;   // 4,096,000
    const int nw4 = F_SZ * K_SZ / 4;    // 32,768
    convert_split_kernel<<<(nx4 + 255) / 256, 256>>>((const float4*)x, p_xhi, p_xlo, nx4);
    convert_split_kernel<<<(nw4 + 255) / 256, 256>>>((const float4*)wts, p_whi, p_wlo, nw4);

    dim3 grid(MROWS / TM, F_SZ / TN);   // (500, 4)
    snn_gemm_kernel<<<grid, GT, SMEM_TOTAL>>>();
    snn_scan_kernel<<<(B_SZ * F_SZ) / 512, 512>>>();
    snn_decode_kernel<<<B_SZ, 320>>>(dec_w, dec_b, out);
}